// round 9
// baseline (speedup 1.0000x reference)
#include <cuda_runtime.h>
#include <cuda_bf16.h>
#include <math.h>
#include <cstdint>

#define D     256
#define NMAX  8192
#define BM    128
#define BN    128
#define NB    (NMAX / BM)     // 64 m-blocks per matrix
#define NT    (NMAX / BN)     // 64 j-tiles per m-block
#define TOTAL_TILES (2 * NB * NT)   // 8192
#define GRID_GEMM 148
#define INVT  20.0f            // 1 / 0.05
#define PITCH 512              // smem row pitch (swizzled, conflict-free)
#define TILE_BYTES (BM * PITCH)        // 65536
#define SMEM_TOTAL (3 * TILE_BYTES)    // 196608 (3-stage B pipeline)

// ---------------------------------------------------------------------------
// Scratch (__device__ globals: allocation-free rule)
// ---------------------------------------------------------------------------
__device__ float g_spos[NMAX];
__device__ float g_rs1[NMAX];
__device__ float g_rs2[NMAX];
__device__ unsigned int g_ticket;
__device__ __align__(16) __nv_bfloat16 g_Ebf[NMAX * D];
__device__ __align__(16) __nv_bfloat16 g_Pbf[NMAX * D];
__device__ __align__(16) __nv_bfloat16 g_Nbf[NMAX * D];

__device__ __forceinline__ uint32_t smem_to_u32(const void* p) {
    uint32_t a;
    asm("{ .reg .u64 t; cvta.to.shared.u64 t, %1; cvt.u32.u64 %0, t; }" : "=r"(a) : "l"(p));
    return a;
}

// swizzled byte offset for (row, 16B-chunk c16), c16 in 0..31
__device__ __forceinline__ uint32_t off16(uint32_t r, uint32_t c16) {
    return r * PITCH + ((((c16 & 7u) ^ (r & 7u)) | (c16 & 24u)) << 4);
}

__device__ __forceinline__ void mma16816(float* d, const uint32_t* a, uint32_t b0, uint32_t b1) {
    asm volatile(
        "mma.sync.aligned.m16n8k16.row.col.f32.bf16.bf16.f32 "
        "{%0,%1,%2,%3}, {%4,%5,%6,%7}, {%8,%9}, {%0,%1,%2,%3};"
        : "+f"(d[0]), "+f"(d[1]), "+f"(d[2]), "+f"(d[3])
        : "r"(a[0]), "r"(a[1]), "r"(a[2]), "r"(a[3]), "r"(b0), "r"(b1));
}

#define LDSM_X4(r, addr) \
    asm volatile("ldmatrix.sync.aligned.m8n8.x4.shared.b16 {%0,%1,%2,%3}, [%4];" \
        : "=r"((r)[0]), "=r"((r)[1]), "=r"((r)[2]), "=r"((r)[3]) : "r"(addr))

// issue one 128x256 bf16 tile (gmem row pitch 512B) into swizzled smem via cp.async
__device__ __forceinline__ void issue_tile(uint32_t sdst, const __nv_bfloat16* src, int tid) {
    #pragma unroll
    for (int i = 0; i < 16; i++) {
        int flat = tid + (i << 8);
        uint32_t r = (uint32_t)flat >> 5, c = (uint32_t)flat & 31;
        uint32_t d = sdst + off16(r, c);
        const char* g = (const char*)src + r * 512 + c * 16;
        asm volatile("cp.async.cg.shared.global [%0], [%1], 16;" :: "r"(d), "l"(g));
    }
}

// ---------------------------------------------------------------------------
// Kernel 1: normalize, 2 rows/warp; zeroes rs accumulators and the ticket.
// ---------------------------------------------------------------------------
__global__ void normalize_kernel(const float* __restrict__ e,
                                 const float* __restrict__ p,
                                 const float* __restrict__ nn) {
    int warp = (blockIdx.x * blockDim.x + threadIdx.x) >> 5;
    int lane = threadIdx.x & 31;
    int row0 = warp * 2;

    if (lane < 2) { g_rs1[row0 + lane] = 0.f; g_rs2[row0 + lane] = 0.f; }
    if (blockIdx.x == 0 && threadIdx.x == 0) g_ticket = 0u;

    float ve[2][8], vp[2][8], vn[2][8];
    #pragma unroll
    for (int rr = 0; rr < 2; rr++) {
        size_t base = (size_t)(row0 + rr) * D + lane * 8;
        *(float4*)&ve[rr][0] = *(const float4*)(e + base);
        *(float4*)&ve[rr][4] = *(const float4*)(e + base + 4);
        *(float4*)&vp[rr][0] = *(const float4*)(p + base);
        *(float4*)&vp[rr][4] = *(const float4*)(p + base + 4);
        *(float4*)&vn[rr][0] = *(const float4*)(nn + base);
        *(float4*)&vn[rr][4] = *(const float4*)(nn + base + 4);
    }

    float se[2] = {0.f, 0.f}, sp[2] = {0.f, 0.f}, sn[2] = {0.f, 0.f};
    #pragma unroll
    for (int rr = 0; rr < 2; rr++)
        #pragma unroll
        for (int i = 0; i < 8; i++) {
            se[rr] += ve[rr][i]*ve[rr][i];
            sp[rr] += vp[rr][i]*vp[rr][i];
            sn[rr] += vn[rr][i]*vn[rr][i];
        }
    #pragma unroll
    for (int o = 16; o > 0; o >>= 1)
        #pragma unroll
        for (int rr = 0; rr < 2; rr++) {
            se[rr] += __shfl_xor_sync(0xffffffffu, se[rr], o);
            sp[rr] += __shfl_xor_sync(0xffffffffu, sp[rr], o);
            sn[rr] += __shfl_xor_sync(0xffffffffu, sn[rr], o);
        }

    float dps[2];
    #pragma unroll
    for (int rr = 0; rr < 2; rr++) {
        float ie = 1.f / fmaxf(sqrtf(se[rr]), 1e-8f);
        float ip = 1.f / fmaxf(sqrtf(sp[rr]), 1e-8f);
        float iv = 1.f / fmaxf(sqrtf(sn[rr]), 1e-8f);
        float d = 0.f;
        __nv_bfloat162 be[4], bp[4], bn[4];
        #pragma unroll
        for (int i = 0; i < 4; i++) {
            float e0 = ve[rr][2*i]*ie,  e1 = ve[rr][2*i+1]*ie;
            float p0 = vp[rr][2*i]*ip,  p1 = vp[rr][2*i+1]*ip;
            float n0 = vn[rr][2*i]*iv,  n1 = vn[rr][2*i+1]*iv;
            d += e0*p0 + e1*p1;
            be[i] = __float22bfloat162_rn(make_float2(e0, e1));
            bp[i] = __float22bfloat162_rn(make_float2(p0, p1));
            bn[i] = __float22bfloat162_rn(make_float2(n0, n1));
        }
        size_t base = (size_t)(row0 + rr) * D + lane * 8;
        *(uint4*)(g_Ebf + base) = *(uint4*)be;
        *(uint4*)(g_Pbf + base) = *(uint4*)bp;
        *(uint4*)(g_Nbf + base) = *(uint4*)bn;
        dps[rr] = d;
    }
    #pragma unroll
    for (int o = 16; o > 0; o >>= 1) {
        dps[0] += __shfl_xor_sync(0xffffffffu, dps[0], o);
        dps[1] += __shfl_xor_sync(0xffffffffu, dps[1], o);
    }
    if (lane == 0) { g_spos[row0] = dps[0]; g_spos[row0 + 1] = dps[1]; }
}

// ---------------------------------------------------------------------------
// Kernel 2: persistent HMMA GEMM + fused exp row-sum + fused finalize.
// R6 mainloop (halves, per-half epilogue, bf double-buffer), single barrier
// per tile. Last CTA to finish (ticket) computes the scalar loss.
// ---------------------------------------------------------------------------
__global__ void __launch_bounds__(256, 1) gemm_expsum_mma(float* __restrict__ out) {
    extern __shared__ char smem[];
    const uint32_t sbase = smem_to_u32(smem);
    const int tid  = threadIdx.x;
    const int wid  = tid >> 5, lane = tid & 31;

    const int warpM = (wid & 3) * 32;
    const int warpN = (wid >> 2) * 64;

    const uint32_t arow = (lane & 7) + ((lane >> 3) & 1) * 8;
    const uint32_t khi  = (uint32_t)(lane >> 4);
    const uint32_t brow = (lane & 7) + (lane >> 4) * 8;
    const uint32_t bhi  = (uint32_t)((lane >> 3) & 1);

    int t   = (int)(((long long)blockIdx.x * TOTAL_TILES) / GRID_GEMM);
    int end = (int)(((long long)(blockIdx.x + 1) * TOTAL_TILES) / GRID_GEMM);

    while (t < end) {
        const int ab  = t >> 6;
        const int j0  = t & 63;
        const int seg = min(NT - j0, end - t);
        const int j1  = j0 + seg;
        const int mat = ab >> 6;
        const int bm  = ab & (NB - 1);
        const __nv_bfloat16* A = mat ? g_Pbf : g_Ebf;
        const __nv_bfloat16* B = mat ? g_Ebf : g_Nbf;
        float* rs = mat ? g_rs2 : g_rs1;
        const int row0 = bm * BM;

        // ---- stage A tile into buf0 (swizzled), read frags into registers
        {
            const uint4* g = (const uint4*)(A + (size_t)row0 * D);
            #pragma unroll
            for (int i = 0; i < 16; i++) {
                int flat = tid + (i << 8);
                uint32_t r = (uint32_t)flat >> 5, c = (uint32_t)flat & 31;
                *(uint4*)(smem + off16(r, c)) = g[r * 32 + c];
            }
        }
        __syncthreads();

        uint32_t aF[2][16][4];
        #pragma unroll
        for (int mt = 0; mt < 2; mt++) {
            uint32_t row = (uint32_t)(warpM + mt * 16) + arow;
            #pragma unroll
            for (int k = 0; k < 16; k++)
                LDSM_X4(aF[mt][k], sbase + off16(row, 2u * k + khi));
        }
        __syncthreads();

        // ---- prologue: 2 B tiles in flight
        issue_tile(sbase, B + (size_t)j0 * BN * D, tid);
        asm volatile("cp.async.commit_group;");
        if (j0 + 1 < j1) {
            issue_tile(sbase + TILE_BYTES, B + (size_t)(j0 + 1) * BN * D, tid);
            asm volatile("cp.async.commit_group;");
        }

        float rowAcc[4] = {0.f, 0.f, 0.f, 0.f};

        for (int j = j0; j < j1; j++) {
            const int sj = j - j0;
            if (j + 1 < j1) asm volatile("cp.async.wait_group 1;" ::: "memory");
            else            asm volatile("cp.async.wait_group 0;" ::: "memory");
            // single barrier: buffer sj%3 visible to all warps AND every warp
            // has finished the previous tile, so buffer (sj+2)%3 is free.
            __syncthreads();
            if (j + 2 < j1) {
                issue_tile(sbase + (uint32_t)((sj + 2) % 3) * TILE_BYTES,
                           B + (size_t)(j + 2) * BN * D, tid);
                asm volatile("cp.async.commit_group;");
            }
            const uint32_t cbase = sbase + (uint32_t)(sj % 3) * TILE_BYTES;

            #pragma unroll
            for (int half = 0; half < 2; half++) {
                float acc[2][4][4];
                #pragma unroll
                for (int mt = 0; mt < 2; mt++)
                    #pragma unroll
                    for (int nt = 0; nt < 4; nt++)
                        #pragma unroll
                        for (int c = 0; c < 4; c++) acc[mt][nt][c] = 0.f;

                const uint32_t rowp0 = (uint32_t)(warpN + (half * 2 + 0) * 16) + brow;
                const uint32_t rowp1 = (uint32_t)(warpN + (half * 2 + 1) * 16) + brow;

                uint32_t bf[2][8];
                LDSM_X4(&bf[0][0], cbase + off16(rowp0, bhi));
                LDSM_X4(&bf[0][4], cbase + off16(rowp1, bhi));
                #pragma unroll
                for (int k = 0; k < 16; k++) {
                    const int c = k & 1, n = c ^ 1;
                    if (k < 15) {
                        uint32_t c16 = 2u * (k + 1) + bhi;
                        LDSM_X4(&bf[n][0], cbase + off16(rowp0, c16));
                        LDSM_X4(&bf[n][4], cbase + off16(rowp1, c16));
                    }
                    #pragma unroll
                    for (int mt = 0; mt < 2; mt++) {
                        mma16816(acc[mt][0], aF[mt][k], bf[c][0], bf[c][1]);
                        mma16816(acc[mt][1], aF[mt][k], bf[c][2], bf[c][3]);
                        mma16816(acc[mt][2], aF[mt][k], bf[c][4], bf[c][5]);
                        mma16816(acc[mt][3], aF[mt][k], bf[c][6], bf[c][7]);
                    }
                }

                // epilogue for this half overlaps next half's MMAs (MUFU hidden)
                #pragma unroll
                for (int mt = 0; mt < 2; mt++)
                    #pragma unroll
                    for (int nt = 0; nt < 4; nt++) {
                        rowAcc[mt*2+0] += __expf(INVT * acc[mt][nt][0]) + __expf(INVT * acc[mt][nt][1]);
                        rowAcc[mt*2+1] += __expf(INVT * acc[mt][nt][2]) + __expf(INVT * acc[mt][nt][3]);
                    }
            }
        }

        // ---- merge partial row sums (quad lanes share rows)
        #pragma unroll
        for (int i = 0; i < 4; i++) {
            rowAcc[i] += __shfl_xor_sync(0xffffffffu, rowAcc[i], 1);
            rowAcc[i] += __shfl_xor_sync(0xffffffffu, rowAcc[i], 2);
        }
        __syncthreads();   // all warps past the mainloop before red[] smem reuse
        float* red = (float*)smem;
        if ((lane & 3) == 0) {
            int rbase = warpM + (lane >> 2);
            int wn = wid >> 2;
            red[(rbase +  0) * 2 + wn] = rowAcc[0];
            red[(rbase +  8) * 2 + wn] = rowAcc[1];
            red[(rbase + 16) * 2 + wn] = rowAcc[2];
            red[(rbase + 24) * 2 + wn] = rowAcc[3];
        }
        __syncthreads();
        if (tid < BM) atomicAdd(&rs[row0 + tid], red[tid * 2] + red[tid * 2 + 1]);
        __syncthreads();

        t += seg;
    }

    // ---- fused finalize: last CTA computes the scalar loss
    __shared__ unsigned int s_last;
    __shared__ float sh[8];
    __threadfence();                       // publish rs atomics
    __syncthreads();
    if (tid == 0) s_last = (atomicAdd(&g_ticket, 1u) == GRID_GEMM - 1u) ? 1u : 0u;
    __syncthreads();
    if (s_last) {
        __threadfence();                   // acquire: see all CTAs' rs updates
        float s = 0.f;
        for (int i = tid; i < NMAX; i += 256) {
            float sp = g_spos[i] * INVT;
            s += log1pf(__expf(-sp) * g_rs1[i]) + (logf(g_rs2[i]) - sp);
        }
        #pragma unroll
        for (int o = 16; o > 0; o >>= 1) s += __shfl_xor_sync(0xffffffffu, s, o);
        if (lane == 0) sh[wid] = s;
        __syncthreads();
        if (wid == 0) {
            float r = (lane < 8) ? sh[lane] : 0.f;
            #pragma unroll
            for (int o = 4; o > 0; o >>= 1) r += __shfl_xor_sync(0xffffffffu, r, o);
            if (lane == 0) out[0] = r / (float)NMAX;
        }
    }
}

// ---------------------------------------------------------------------------
extern "C" void kernel_launch(void* const* d_in, const int* in_sizes, int n_in,
                              void* d_out, int out_size) {
    const float* e  = (const float*)d_in[0];
    const float* p  = (const float*)d_in[1];
    const float* nn = (const float*)d_in[2];
    const int N = in_sizes[0] / D;   // 8192

    static bool attr_set = false;
    if (!attr_set) {
        cudaFuncSetAttribute(gemm_expsum_mma, cudaFuncAttributeMaxDynamicSharedMemorySize, SMEM_TOTAL);
        attr_set = true;
    }

    normalize_kernel<<<N / 16, 256>>>(e, p, nn);
    gemm_expsum_mma<<<GRID_GEMM, 256, SMEM_TOTAL>>>((float*)d_out);
}

// round 10
// speedup vs baseline: 1.2441x; 1.2441x over previous
#include <cuda_runtime.h>
#include <cuda_bf16.h>
#include <math.h>
#include <cstdint>

#define D     256
#define NMAX  8192
#define BM    128
#define BN    128
#define NB    (NMAX / BM)     // 64 m-blocks per matrix
#define NT    (NMAX / BN)     // 64 j-tiles per m-block
#define TOTAL_TILES (2 * NB * NT)   // 8192
#define GRID_GEMM 148
#define INVT  20.0f            // 1 / 0.05
#define PITCH 512              // smem row pitch (swizzled, conflict-free)
#define TILE_BYTES (BM * PITCH)        // 65536
#define SMEM_TOTAL (3 * TILE_BYTES)    // 196608 (3-stage B pipeline)

// ---------------------------------------------------------------------------
// Scratch (__device__ globals: allocation-free rule)
// ---------------------------------------------------------------------------
__device__ float g_spos[NMAX];
__device__ float g_rs1[NMAX];
__device__ float g_rs2[NMAX];
__device__ __align__(16) __nv_bfloat16 g_Ebf[NMAX * D];
__device__ __align__(16) __nv_bfloat16 g_Pbf[NMAX * D];
__device__ __align__(16) __nv_bfloat16 g_Nbf[NMAX * D];

__device__ __forceinline__ uint32_t smem_to_u32(const void* p) {
    uint32_t a;
    asm("{ .reg .u64 t; cvta.to.shared.u64 t, %1; cvt.u32.u64 %0, t; }" : "=r"(a) : "l"(p));
    return a;
}

// swizzled byte offset for (row, 16B-chunk c16), c16 in 0..31
__device__ __forceinline__ uint32_t off16(uint32_t r, uint32_t c16) {
    return r * PITCH + ((((c16 & 7u) ^ (r & 7u)) | (c16 & 24u)) << 4);
}

__device__ __forceinline__ void mma16816(float* d, const uint32_t* a, uint32_t b0, uint32_t b1) {
    asm volatile(
        "mma.sync.aligned.m16n8k16.row.col.f32.bf16.bf16.f32 "
        "{%0,%1,%2,%3}, {%4,%5,%6,%7}, {%8,%9}, {%0,%1,%2,%3};"
        : "+f"(d[0]), "+f"(d[1]), "+f"(d[2]), "+f"(d[3])
        : "r"(a[0]), "r"(a[1]), "r"(a[2]), "r"(a[3]), "r"(b0), "r"(b1));
}

#define LDSM_X4(r, addr) \
    asm volatile("ldmatrix.sync.aligned.m8n8.x4.shared.b16 {%0,%1,%2,%3}, [%4];" \
        : "=r"((r)[0]), "=r"((r)[1]), "=r"((r)[2]), "=r"((r)[3]) : "r"(addr))

// issue one 128x256 bf16 tile (gmem row pitch 512B) into swizzled smem via cp.async
__device__ __forceinline__ void issue_tile(uint32_t sdst, const __nv_bfloat16* src, int tid) {
    #pragma unroll
    for (int i = 0; i < 16; i++) {
        int flat = tid + (i << 8);
        uint32_t r = (uint32_t)flat >> 5, c = (uint32_t)flat & 31;
        uint32_t d = sdst + off16(r, c);
        const char* g = (const char*)src + r * 512 + c * 16;
        asm volatile("cp.async.cg.shared.global [%0], [%1], 16;" :: "r"(d), "l"(g));
    }
}

// ---------------------------------------------------------------------------
// Kernel 1: normalize, 2 rows/warp; zeroes rs accumulators and d_out.
// ---------------------------------------------------------------------------
__global__ void normalize_kernel(const float* __restrict__ e,
                                 const float* __restrict__ p,
                                 const float* __restrict__ nn,
                                 float* __restrict__ out) {
    int warp = (blockIdx.x * blockDim.x + threadIdx.x) >> 5;
    int lane = threadIdx.x & 31;
    int row0 = warp * 2;

    if (lane < 2) { g_rs1[row0 + lane] = 0.f; g_rs2[row0 + lane] = 0.f; }
    if (blockIdx.x == 0 && threadIdx.x == 0) out[0] = 0.f;

    float ve[2][8], vp[2][8], vn[2][8];
    #pragma unroll
    for (int rr = 0; rr < 2; rr++) {
        size_t base = (size_t)(row0 + rr) * D + lane * 8;
        *(float4*)&ve[rr][0] = *(const float4*)(e + base);
        *(float4*)&ve[rr][4] = *(const float4*)(e + base + 4);
        *(float4*)&vp[rr][0] = *(const float4*)(p + base);
        *(float4*)&vp[rr][4] = *(const float4*)(p + base + 4);
        *(float4*)&vn[rr][0] = *(const float4*)(nn + base);
        *(float4*)&vn[rr][4] = *(const float4*)(nn + base + 4);
    }

    float se[2] = {0.f, 0.f}, sp[2] = {0.f, 0.f}, sn[2] = {0.f, 0.f};
    #pragma unroll
    for (int rr = 0; rr < 2; rr++)
        #pragma unroll
        for (int i = 0; i < 8; i++) {
            se[rr] += ve[rr][i]*ve[rr][i];
            sp[rr] += vp[rr][i]*vp[rr][i];
            sn[rr] += vn[rr][i]*vn[rr][i];
        }
    #pragma unroll
    for (int o = 16; o > 0; o >>= 1)
        #pragma unroll
        for (int rr = 0; rr < 2; rr++) {
            se[rr] += __shfl_xor_sync(0xffffffffu, se[rr], o);
            sp[rr] += __shfl_xor_sync(0xffffffffu, sp[rr], o);
            sn[rr] += __shfl_xor_sync(0xffffffffu, sn[rr], o);
        }

    float dps[2];
    #pragma unroll
    for (int rr = 0; rr < 2; rr++) {
        float ie = 1.f / fmaxf(sqrtf(se[rr]), 1e-8f);
        float ip = 1.f / fmaxf(sqrtf(sp[rr]), 1e-8f);
        float iv = 1.f / fmaxf(sqrtf(sn[rr]), 1e-8f);
        float d = 0.f;
        __nv_bfloat162 be[4], bp[4], bn[4];
        #pragma unroll
        for (int i = 0; i < 4; i++) {
            float e0 = ve[rr][2*i]*ie,  e1 = ve[rr][2*i+1]*ie;
            float p0 = vp[rr][2*i]*ip,  p1 = vp[rr][2*i+1]*ip;
            float n0 = vn[rr][2*i]*iv,  n1 = vn[rr][2*i+1]*iv;
            d += e0*p0 + e1*p1;
            be[i] = __float22bfloat162_rn(make_float2(e0, e1));
            bp[i] = __float22bfloat162_rn(make_float2(p0, p1));
            bn[i] = __float22bfloat162_rn(make_float2(n0, n1));
        }
        size_t base = (size_t)(row0 + rr) * D + lane * 8;
        *(uint4*)(g_Ebf + base) = *(uint4*)be;
        *(uint4*)(g_Pbf + base) = *(uint4*)bp;
        *(uint4*)(g_Nbf + base) = *(uint4*)bn;
        dps[rr] = d;
    }
    #pragma unroll
    for (int o = 16; o > 0; o >>= 1) {
        dps[0] += __shfl_xor_sync(0xffffffffu, dps[0], o);
        dps[1] += __shfl_xor_sync(0xffffffffu, dps[1], o);
    }
    if (lane == 0) { g_spos[row0] = dps[0]; g_spos[row0 + 1] = dps[1]; }
}

// ---------------------------------------------------------------------------
// Kernel 2: persistent HMMA GEMM + fused exp row-sum (R6 mainloop).
// A staged into buf2 AFTER B prefetch is issued (hides segment-start B latency);
// single barrier per tile (top-of-iteration sync proves refill buffer free).
// ---------------------------------------------------------------------------
__global__ void __launch_bounds__(256, 1) gemm_expsum_mma() {
    extern __shared__ char smem[];
    const uint32_t sbase = smem_to_u32(smem);
    const int tid  = threadIdx.x;
    const int wid  = tid >> 5, lane = tid & 31;

    const int warpM = (wid & 3) * 32;
    const int warpN = (wid >> 2) * 64;

    const uint32_t arow = (lane & 7) + ((lane >> 3) & 1) * 8;
    const uint32_t khi  = (uint32_t)(lane >> 4);
    const uint32_t brow = (lane & 7) + (lane >> 4) * 8;
    const uint32_t bhi  = (uint32_t)((lane >> 3) & 1);

    int t   = (int)(((long long)blockIdx.x * TOTAL_TILES) / GRID_GEMM);
    int end = (int)(((long long)(blockIdx.x + 1) * TOTAL_TILES) / GRID_GEMM);

    while (t < end) {
        const int ab  = t >> 6;
        const int j0  = t & 63;
        const int seg = min(NT - j0, end - t);
        const int j1  = j0 + seg;
        const int mat = ab >> 6;
        const int bm  = ab & (NB - 1);
        const __nv_bfloat16* A = mat ? g_Pbf : g_Ebf;
        const __nv_bfloat16* B = mat ? g_Ebf : g_Nbf;
        float* rs = mat ? g_rs2 : g_rs1;
        const int row0 = bm * BM;

        // ---- prefetch first two B tiles (buf0, buf1) BEFORE staging A
        issue_tile(sbase, B + (size_t)j0 * BN * D, tid);
        asm volatile("cp.async.commit_group;");
        if (j0 + 1 < j1) {
            issue_tile(sbase + TILE_BYTES, B + (size_t)(j0 + 1) * BN * D, tid);
            asm volatile("cp.async.commit_group;");
        }

        // ---- stage A tile into buf2 (swizzled), read frags into registers.
        // buf2's first refill is at iteration 0's top, after the aF-load sync.
        {
            const uint4* g = (const uint4*)(A + (size_t)row0 * D);
            char* adst = smem + 2 * TILE_BYTES;
            #pragma unroll
            for (int i = 0; i < 16; i++) {
                int flat = tid + (i << 8);
                uint32_t r = (uint32_t)flat >> 5, c = (uint32_t)flat & 31;
                *(uint4*)(adst + off16(r, c)) = g[r * 32 + c];
            }
        }
        __syncthreads();

        uint32_t aF[2][16][4];
        #pragma unroll
        for (int mt = 0; mt < 2; mt++) {
            uint32_t row = (uint32_t)(warpM + mt * 16) + arow;
            #pragma unroll
            for (int k = 0; k < 16; k++)
                LDSM_X4(aF[mt][k], sbase + 2u * TILE_BYTES + off16(row, 2u * k + khi));
        }
        __syncthreads();

        float rowAcc[4] = {0.f, 0.f, 0.f, 0.f};

        for (int j = j0; j < j1; j++) {
            const int sj = j - j0;
            if (j + 1 < j1) asm volatile("cp.async.wait_group 1;" ::: "memory");
            else            asm volatile("cp.async.wait_group 0;" ::: "memory");
            // single barrier: buffer sj%3 visible AND every warp finished tile
            // sj-1, so buffer (sj+2)%3 (== (sj-1)%3) is free for refill.
            __syncthreads();
            if (j + 2 < j1) {
                issue_tile(sbase + (uint32_t)((sj + 2) % 3) * TILE_BYTES,
                           B + (size_t)(j + 2) * BN * D, tid);
                asm volatile("cp.async.commit_group;");
            }
            const uint32_t cbase = sbase + (uint32_t)(sj % 3) * TILE_BYTES;

            #pragma unroll
            for (int half = 0; half < 2; half++) {
                float acc[2][4][4];
                #pragma unroll
                for (int mt = 0; mt < 2; mt++)
                    #pragma unroll
                    for (int nt = 0; nt < 4; nt++)
                        #pragma unroll
                        for (int c = 0; c < 4; c++) acc[mt][nt][c] = 0.f;

                const uint32_t rowp0 = (uint32_t)(warpN + (half * 2 + 0) * 16) + brow;
                const uint32_t rowp1 = (uint32_t)(warpN + (half * 2 + 1) * 16) + brow;

                uint32_t bf[2][8];
                LDSM_X4(&bf[0][0], cbase + off16(rowp0, bhi));
                LDSM_X4(&bf[0][4], cbase + off16(rowp1, bhi));
                #pragma unroll
                for (int k = 0; k < 16; k++) {
                    const int c = k & 1, n = c ^ 1;
                    if (k < 15) {
                        uint32_t c16 = 2u * (k + 1) + bhi;
                        LDSM_X4(&bf[n][0], cbase + off16(rowp0, c16));
                        LDSM_X4(&bf[n][4], cbase + off16(rowp1, c16));
                    }
                    #pragma unroll
                    for (int mt = 0; mt < 2; mt++) {
                        mma16816(acc[mt][0], aF[mt][k], bf[c][0], bf[c][1]);
                        mma16816(acc[mt][1], aF[mt][k], bf[c][2], bf[c][3]);
                        mma16816(acc[mt][2], aF[mt][k], bf[c][4], bf[c][5]);
                        mma16816(acc[mt][3], aF[mt][k], bf[c][6], bf[c][7]);
                    }
                }

                // epilogue for this half overlaps next half's MMAs (MUFU hidden)
                #pragma unroll
                for (int mt = 0; mt < 2; mt++)
                    #pragma unroll
                    for (int nt = 0; nt < 4; nt++) {
                        rowAcc[mt*2+0] += __expf(INVT * acc[mt][nt][0]) + __expf(INVT * acc[mt][nt][1]);
                        rowAcc[mt*2+1] += __expf(INVT * acc[mt][nt][2]) + __expf(INVT * acc[mt][nt][3]);
                    }
            }
        }

        // ---- merge partial row sums (quad lanes share rows)
        #pragma unroll
        for (int i = 0; i < 4; i++) {
            rowAcc[i] += __shfl_xor_sync(0xffffffffu, rowAcc[i], 1);
            rowAcc[i] += __shfl_xor_sync(0xffffffffu, rowAcc[i], 2);
        }
        __syncthreads();   // all warps past mainloop before red[] smem reuse
        float* red = (float*)smem;
        if ((lane & 3) == 0) {
            int rbase = warpM + (lane >> 2);
            int wn = wid >> 2;
            red[(rbase +  0) * 2 + wn] = rowAcc[0];
            red[(rbase +  8) * 2 + wn] = rowAcc[1];
            red[(rbase + 16) * 2 + wn] = rowAcc[2];
            red[(rbase + 24) * 2 + wn] = rowAcc[3];
        }
        __syncthreads();
        if (tid < BM) atomicAdd(&rs[row0 + tid], red[tid * 2] + red[tid * 2 + 1]);
        __syncthreads();

        t += seg;
    }
}

// ---------------------------------------------------------------------------
// Kernel 3: parallel loss assembly; partial block sums merged via atomicAdd.
// ---------------------------------------------------------------------------
__global__ void finalize_kernel(float* __restrict__ out, int N) {
    __shared__ float sh[32];
    int i = blockIdx.x * blockDim.x + threadIdx.x;
    float s = 0.f;
    if (i < N) {
        float sp = g_spos[i] * INVT;
        s = log1pf(__expf(-sp) * g_rs1[i]) + (logf(g_rs2[i]) - sp);
    }
    int lane = threadIdx.x & 31, w = threadIdx.x >> 5;
    #pragma unroll
    for (int o = 16; o > 0; o >>= 1) s += __shfl_xor_sync(0xffffffffu, s, o);
    if (lane == 0) sh[w] = s;
    __syncthreads();
    if (w == 0) {
        float r = (lane < (int)(blockDim.x >> 5)) ? sh[lane] : 0.f;
        #pragma unroll
        for (int o = 16; o > 0; o >>= 1) r += __shfl_xor_sync(0xffffffffu, r, o);
        if (lane == 0) atomicAdd(out, r / (float)N);
    }
}

// ---------------------------------------------------------------------------
extern "C" void kernel_launch(void* const* d_in, const int* in_sizes, int n_in,
                              void* d_out, int out_size) {
    const float* e  = (const float*)d_in[0];
    const float* p  = (const float*)d_in[1];
    const float* nn = (const float*)d_in[2];
    const int N = in_sizes[0] / D;   // 8192

    static bool attr_set = false;
    if (!attr_set) {
        cudaFuncSetAttribute(gemm_expsum_mma, cudaFuncAttributeMaxDynamicSharedMemorySize, SMEM_TOTAL);
        attr_set = true;
    }

    normalize_kernel<<<N / 16, 256>>>(e, p, nn, (float*)d_out);
    gemm_expsum_mma<<<GRID_GEMM, 256, SMEM_TOTAL>>>();
    finalize_kernel<<<N / 1024, 1024>>>((float*)d_out, N);
}